// round 1
// baseline (speedup 1.0000x reference)
#include <cuda_runtime.h>
#include <cuda_bf16.h>
#include <cstddef>

// Problem constants (fixed by the dataset): N=100000, E=1000000, F=64, H=8, D=8
#define MAXN 100000
#define CLIPV 5.0f
#define INV_SQRT_D 0.35355339059327373f

// ---------------- scratch (device globals: allocation-free rule) -------------
__device__ float g_Q[(size_t)MAXN * 64];
__device__ float g_K[(size_t)MAXN * 64];
__device__ float g_V[(size_t)MAXN * 64];
// per-node accumulator: 64 floats wV + 8 floats z, stride 72 (288B, 16B-aligned)
__device__ float g_acc[(size_t)MAXN * 72];

// ---------------- packed f32x2 helpers --------------------------------------
__device__ __forceinline__ unsigned long long fma2(unsigned long long a,
                                                   unsigned long long b,
                                                   unsigned long long c) {
    unsigned long long d;
    asm("fma.rn.f32x2 %0, %1, %2, %3;" : "=l"(d) : "l"(a), "l"(b), "l"(c));
    return d;
}
__device__ __forceinline__ float pairsum(unsigned long long v) {
    float lo, hi;
    asm("mov.b64 {%0, %1}, %2;" : "=f"(lo), "=f"(hi) : "l"(v));
    return lo + hi;
}
__device__ __forceinline__ void red4(float* p, float a, float b, float c, float d) {
    asm volatile("red.global.add.v4.f32 [%0], {%1, %2, %3, %4};"
                 :: "l"(p), "f"(a), "f"(b), "f"(c), "f"(d) : "memory");
}
__device__ __forceinline__ float clipf(float x) {
    return fminf(fmaxf(x, -CLIPV), CLIPV);
}

// ---------------- kernel 1: node projections Q,K,V ---------------------------
// thread = one node; x row in 64 registers (32 packed f32x2);
// weights warp-uniform from smem (LDS.128), FMA pipe is the binder.
__device__ __forceinline__ void proj_row64(const unsigned long long* __restrict__ x2,
                                           const unsigned long long* __restrict__ wm, // smem, 32 ull per row
                                           const float* __restrict__ bias,           // global, L1-cached
                                           float* __restrict__ o) {
    #pragma unroll 1
    for (int g = 0; g < 16; g++) {
        const unsigned long long* wr = wm + (size_t)(4 * g) * 32;
        unsigned long long a0 = 0ull, a1 = 0ull, a2 = 0ull, a3 = 0ull;
        #pragma unroll
        for (int kk = 0; kk < 32; kk += 2) {
            ulonglong2 w0 = *reinterpret_cast<const ulonglong2*>(wr + kk);
            ulonglong2 w1 = *reinterpret_cast<const ulonglong2*>(wr + 32 + kk);
            ulonglong2 w2 = *reinterpret_cast<const ulonglong2*>(wr + 64 + kk);
            ulonglong2 w3 = *reinterpret_cast<const ulonglong2*>(wr + 96 + kk);
            unsigned long long xa = x2[kk], xb = x2[kk + 1];
            a0 = fma2(xa, w0.x, a0); a0 = fma2(xb, w0.y, a0);
            a1 = fma2(xa, w1.x, a1); a1 = fma2(xb, w1.y, a1);
            a2 = fma2(xa, w2.x, a2); a2 = fma2(xb, w2.y, a2);
            a3 = fma2(xa, w3.x, a3); a3 = fma2(xb, w3.y, a3);
        }
        float4 bv = __ldg(reinterpret_cast<const float4*>(bias + 4 * g));
        float4 r;
        r.x = pairsum(a0) + bv.x;
        r.y = pairsum(a1) + bv.y;
        r.z = pairsum(a2) + bv.z;
        r.w = pairsum(a3) + bv.w;
        *reinterpret_cast<float4*>(o + 4 * g) = r;
    }
}

__global__ __launch_bounds__(256, 2)
void node_proj_kernel(const float* __restrict__ nf,
                      const float* __restrict__ Wq, const float* __restrict__ bq,
                      const float* __restrict__ Wk, const float* __restrict__ bk,
                      const float* __restrict__ Wv, const float* __restrict__ bv,
                      int N) {
    __shared__ float sW[3 * 4096];  // 48KB exactly
    for (int i = threadIdx.x; i < 4096; i += 256) {
        sW[i]        = Wq[i];
        sW[4096 + i] = Wk[i];
        sW[8192 + i] = Wv[i];
    }
    __syncthreads();

    int n = blockIdx.x * 256 + threadIdx.x;
    if (n >= N) return;

    unsigned long long x2[32];
    const ulonglong2* xp = reinterpret_cast<const ulonglong2*>(nf + (size_t)n * 64);
    #pragma unroll
    for (int i = 0; i < 16; i++) { ulonglong2 v = xp[i]; x2[2 * i] = v.x; x2[2 * i + 1] = v.y; }

    const unsigned long long* wbase = reinterpret_cast<const unsigned long long*>(sW);
    proj_row64(x2, wbase,            bq, g_Q + (size_t)n * 64);
    proj_row64(x2, wbase + 2048,     bk, g_K + (size_t)n * 64);
    proj_row64(x2, wbase + 4096,     bv, g_V + (size_t)n * 64);
}

// ---------------- kernel 2: edge kernel --------------------------------------
// thread = one edge.
//   1. score[h] = clip( (K[src] . Q[dst])_h / sqrt(D) )
//   2. pe = edge_feats[e] @ We^T + be  (packed f32x2, 2048 FFMA2/thread)
//      s  = score[h] * pe  -> e_out; ssum[h] += s
//   3. w[h] = exp(clip(ssum[h])); red.v4 scatter of V[src]*w and w into g_acc[dst]
__global__ __launch_bounds__(256, 2)
void edge_kernel(const float* __restrict__ ef,
                 const int* __restrict__ src, const int* __restrict__ dst,
                 const float* __restrict__ We, const float* __restrict__ be,
                 float* __restrict__ e_out, int E) {
    __shared__ float sW[4096];
    __shared__ float sb[64];
    for (int i = threadIdx.x; i < 4096; i += 256) sW[i] = We[i];
    if (threadIdx.x < 64) sb[threadIdx.x] = be[threadIdx.x];
    __syncthreads();

    int e = blockIdx.x * 256 + threadIdx.x;
    if (e >= E) return;

    // load edge features packed
    unsigned long long x2[32];
    const ulonglong2* xp = reinterpret_cast<const ulonglong2*>(ef + (size_t)e * 64);
    #pragma unroll
    for (int i = 0; i < 16; i++) { ulonglong2 v = xp[i]; x2[2 * i] = v.x; x2[2 * i + 1] = v.y; }

    int s = src[e], d = dst[e];

    // per-head attention scores (gathers served from L2-resident g_K/g_Q)
    const float4* Kp = reinterpret_cast<const float4*>(g_K + (size_t)s * 64);
    const float4* Qp = reinterpret_cast<const float4*>(g_Q + (size_t)d * 64);
    float sc[8];
    #pragma unroll
    for (int h = 0; h < 8; h++) {
        float4 k0 = Kp[2 * h], k1 = Kp[2 * h + 1];
        float4 q0 = Qp[2 * h], q1 = Qp[2 * h + 1];
        float acc = k0.x * q0.x + k0.y * q0.y + k0.z * q0.z + k0.w * q0.w
                  + k1.x * q1.x + k1.y * q1.y + k1.z * q1.z + k1.w * q1.w;
        sc[h] = clipf(acc * INV_SQRT_D);
    }

    // edge projection + e_out + per-head row sums
    float ssum[8];
    #pragma unroll
    for (int h = 0; h < 8; h++) ssum[h] = 0.0f;

    float* eo = e_out + (size_t)e * 64;
    const unsigned long long* wm = reinterpret_cast<const unsigned long long*>(sW);

    #pragma unroll 1
    for (int g = 0; g < 16; g++) {
        const unsigned long long* wr = wm + (size_t)(4 * g) * 32;
        unsigned long long a0 = 0ull, a1 = 0ull, a2 = 0ull, a3 = 0ull;
        #pragma unroll
        for (int kk = 0; kk < 32; kk += 2) {
            ulonglong2 w0 = *reinterpret_cast<const ulonglong2*>(wr + kk);
            ulonglong2 w1 = *reinterpret_cast<const ulonglong2*>(wr + 32 + kk);
            ulonglong2 w2 = *reinterpret_cast<const ulonglong2*>(wr + 64 + kk);
            ulonglong2 w3 = *reinterpret_cast<const ulonglong2*>(wr + 96 + kk);
            unsigned long long xa = x2[kk], xb = x2[kk + 1];
            a0 = fma2(xa, w0.x, a0); a0 = fma2(xb, w0.y, a0);
            a1 = fma2(xa, w1.x, a1); a1 = fma2(xb, w1.y, a1);
            a2 = fma2(xa, w2.x, a2); a2 = fma2(xb, w2.y, a2);
            a3 = fma2(xa, w3.x, a3); a3 = fma2(xb, w3.y, a3);
        }
        int h = g >> 1;
        float scv = sc[h];
        float pe0 = pairsum(a0) + sb[4 * g + 0];
        float pe1 = pairsum(a1) + sb[4 * g + 1];
        float pe2 = pairsum(a2) + sb[4 * g + 2];
        float pe3 = pairsum(a3) + sb[4 * g + 3];
        float4 r;
        r.x = scv * pe0; r.y = scv * pe1; r.z = scv * pe2; r.w = scv * pe3;
        ssum[h] += (r.x + r.y) + (r.z + r.w);
        *reinterpret_cast<float4*>(eo + 4 * g) = r;
    }

    // per-head weights
    float w[8];
    #pragma unroll
    for (int h = 0; h < 8; h++) w[h] = __expf(clipf(ssum[h]));

    // scatter: wV and z via vectorized reductions (coalesced sectors in L2)
    const float4* Vp = reinterpret_cast<const float4*>(g_V + (size_t)s * 64);
    float* ap = g_acc + (size_t)d * 72;
    #pragma unroll
    for (int kk = 0; kk < 16; kk++) {
        float4 v = Vp[kk];
        float wh = w[kk >> 1];
        red4(ap + 4 * kk, v.x * wh, v.y * wh, v.z * wh, v.w * wh);
    }
    red4(ap + 64, w[0], w[1], w[2], w[3]);
    red4(ap + 68, w[4], w[5], w[6], w[7]);
}

// ---------------- kernel 3: finalize h_out = wV / (z + 1e-6) -----------------
__global__ __launch_bounds__(256)
void finalize_kernel(float* __restrict__ h_out, int N) {
    int t = blockIdx.x * 256 + threadIdx.x;
    if (t >= N * 16) return;
    int n = t >> 4, g = t & 15;
    const float* ap = g_acc + (size_t)n * 72;
    float4 wv = *reinterpret_cast<const float4*>(ap + 4 * g);
    float z = ap[64 + (g >> 1)];
    float inv = 1.0f / (z + 1e-6f);
    float4 r;
    r.x = wv.x * inv; r.y = wv.y * inv; r.z = wv.z * inv; r.w = wv.w * inv;
    *reinterpret_cast<float4*>(h_out + (size_t)n * 64 + 4 * g) = r;
}

// ---------------- launch ------------------------------------------------------
extern "C" void kernel_launch(void* const* d_in, const int* in_sizes, int n_in,
                              void* d_out, int out_size) {
    const float* nf = (const float*)d_in[0];
    const float* ef = (const float*)d_in[1];
    const int*   src = (const int*)d_in[2];
    const int*   dst = (const int*)d_in[3];
    const float* Wq = (const float*)d_in[4];
    const float* bq = (const float*)d_in[5];
    const float* Wk = (const float*)d_in[6];
    const float* bk = (const float*)d_in[7];
    const float* Wv = (const float*)d_in[8];
    const float* bv = (const float*)d_in[9];
    const float* We = (const float*)d_in[10];
    const float* be = (const float*)d_in[11];

    int N = in_sizes[0] / 64;
    int E = in_sizes[2];

    float* h_out = (float*)d_out;                  // [N, 64]
    float* e_out = (float*)d_out + (size_t)N * 64; // [E, 64]

    void* accp = nullptr;
    cudaGetSymbolAddress(&accp, g_acc);
    cudaMemsetAsync(accp, 0, (size_t)N * 72 * sizeof(float));

    node_proj_kernel<<<(N + 255) / 256, 256>>>(nf, Wq, bq, Wk, bk, Wv, bv, N);
    edge_kernel<<<(E + 255) / 256, 256>>>(ef, src, dst, We, be, e_out, E);
    finalize_kernel<<<((N * 16) + 255) / 256, 256>>>(h_out, N);
}